// round 6
// baseline (speedup 1.0000x reference)
#include <cuda_runtime.h>
#include <cuda_bf16.h>

// M=64, G=48, N=4096, GRID_RANGE=2.0
// Inputs: 0:x(N) 1:y(N) 2:z(N) 3:mu_x(M*G) 4:mu_y(M*G) 5:mu_z(M*G)
//         6:sigmas(M*G*3) 7:r(M*G*4) 8:weight(M*G)
// Output: float (N, M) row-major.

#define MDIM 64
#define GDIM 48

__device__ __forceinline__ float fast_exp2(float q) {
    float p; asm("ex2.approx.ftz.f32 %0, %1;" : "=f"(p) : "f"(q)); return p;
}

// ---------------- cold path: fully general coefficients ----------------
// Whole block enters together (iso is block-uniform), so __syncthreads is legal.
__device__ __noinline__ void generic_path(
    const float* __restrict__ mu_x, const float* __restrict__ mu_y,
    const float* __restrict__ mu_z, const float* __restrict__ sigmas,
    const float* __restrict__ rq, const float* __restrict__ weight,
    float4* sbuf, int m, int t, float x, float y, float z,
    float* __restrict__ out, int n, int N) {
    if (t < GDIM) {
        const int idx = m * GDIM + t;
        const float4 q4 = reinterpret_cast<const float4*>(rq)[idx];  // w,x,y,z
        const float s0  = sigmas[idx * 3 + 0];
        const float s1  = sigmas[idx * 3 + 1];
        const float s2c = sigmas[idx * 3 + 2];
        const float m0 = mu_x[idx], m1 = mu_y[idx], m2 = mu_z[idx];
        const float w = weight[idx];

        const float inv = rsqrtf(q4.x * q4.x + q4.y * q4.y + q4.z * q4.z + q4.w * q4.w);
        const float nw = q4.x * inv, nx = q4.y * inv, ny = q4.z * inv, nz = q4.w * inv;
        float R[3][3];
        R[0][0] = 1.f - 2.f * (ny * ny + nz * nz);
        R[0][1] = 2.f * (nx * ny - nw * nz);
        R[0][2] = 2.f * (nx * nz + nw * ny);
        R[1][0] = 2.f * (nx * ny + nw * nz);
        R[1][1] = 1.f - 2.f * (nx * nx + nz * nz);
        R[1][2] = 2.f * (ny * nz - nw * nx);
        R[2][0] = 2.f * (nx * nz - nw * ny);
        R[2][1] = 2.f * (ny * nz + nw * nx);
        R[2][2] = 1.f - 2.f * (nx * nx + ny * ny);

        const float is0 = 1.f / (s0 * s0);
        const float is1 = 1.f / (s1 * s1);
        const float is2 = 1.f / (s2c * s2c);

        const float kk = -0.72134752044448169f;  // -0.5 * log2(e)
        float A[3][3];
        #pragma unroll
        for (int i = 0; i < 3; ++i)
            #pragma unroll
            for (int j = 0; j < 3; ++j)
                A[i][j] = kk * (R[i][0] * R[j][0] * is0 +
                                R[i][1] * R[j][1] * is1 +
                                R[i][2] * R[j][2] * is2);

        const float b0 = -2.f * (A[0][0] * m0 + A[0][1] * m1 + A[0][2] * m2);
        const float b1 = -2.f * (A[1][0] * m0 + A[1][1] * m1 + A[1][2] * m2);
        const float b2 = -2.f * (A[2][0] * m0 + A[2][1] * m1 + A[2][2] * m2);
        const float c  = A[0][0] * m0 * m0 + A[1][1] * m1 * m1 + A[2][2] * m2 * m2
                 + 2.f * (A[0][1] * m0 * m1 + A[0][2] * m0 * m2 + A[1][2] * m1 * m2);

        sbuf[t * 3 + 0] = make_float4(A[0][0], A[1][1], A[2][2], 2.f * A[0][1]);
        sbuf[t * 3 + 1] = make_float4(2.f * A[0][2], 2.f * A[1][2], b0, b1);
        sbuf[t * 3 + 2] = make_float4(b2, c, w, 0.f);
    }
    __syncthreads();

    const float xx = x * x, yy = y * y, zz = z * z;
    const float xy = x * y, xz = x * z, yz = y * z;
    float acc = 0.f;
    #pragma unroll 4
    for (int g = 0; g < GDIM; ++g) {
        const float4 cA = sbuf[g * 3 + 0];
        const float4 cB = sbuf[g * 3 + 1];
        const float4 cC = sbuf[g * 3 + 2];
        float q = cC.y;
        q = fmaf(cA.x, xx, q);
        q = fmaf(cA.y, yy, q);
        q = fmaf(cA.z, zz, q);
        q = fmaf(cA.w, xy, q);
        q = fmaf(cB.x, xz, q);
        q = fmaf(cB.y, yz, q);
        q = fmaf(cB.z, x, q);
        q = fmaf(cB.w, y, q);
        q = fmaf(cC.x, z, q);
        acc = fmaf(cC.z, fast_exp2(q), acc);
    }
    if (n < N) out[n * MDIM + m] = acc;
}

// ---------------- hot kernel ----------------
// One m per block (blockIdx.y), 256 points (1/thread), grid.x = 16.
// Iso path: A = a*I common to all g (identity-axis quaternion, uniform sigmas):
//   out = exp2(a*|p|^2) * sum_g (w_g*exp2(c_g)) * exp2(b_g.p)
// hot loop per (g,point): LDS.128 {b0,b1,b2,w'}, 3 FMA, 1 MUFU, 1 acc FMA.
__global__ __launch_bounds__(256, 8) void gauss_fused_kernel(
    const float* __restrict__ xs, const float* __restrict__ ys,
    const float* __restrict__ zs,
    const float* __restrict__ mu_x, const float* __restrict__ mu_y,
    const float* __restrict__ mu_z, const float* __restrict__ sigmas,
    const float* __restrict__ rq, const float* __restrict__ weight,
    float* __restrict__ out, int N) {
    __shared__ __align__(16) float4 sbuf[GDIM * 3];  // iso uses first 48
    __shared__ float s_a;

    const int m = blockIdx.y;
    const int t = threadIdx.x;
    const int n = blockIdx.x * 256 + t;

    // early point loads (independent of coefficient pipeline)
    float x = 0.f, y = 0.f, z = 0.f;
    if (n < N) {
        x = xs[n];
        y = ys[n] + 1.f;   // (y+1)/2 * GRID_RANGE with GRID_RANGE=2
        z = zs[n] + 1.f;
    }

    // iso detection (cheap, from raw inputs)
    int pred = 1;
    float s0 = 0.f, m0 = 0.f, m1 = 0.f, m2 = 0.f, w = 0.f;
    if (t < GDIM) {
        const int idx = m * GDIM + t;
        const float4 q4 = reinterpret_cast<const float4*>(rq)[idx];  // w,x,y,z
        s0 = sigmas[idx * 3 + 0];
        const float s1  = sigmas[idx * 3 + 1];
        const float s2c = sigmas[idx * 3 + 2];
        const float sg0 = sigmas[(m * GDIM) * 3];
        m0 = mu_x[idx]; m1 = mu_y[idx]; m2 = mu_z[idx];
        w = weight[idx];
        pred = (q4.y == 0.f) & (q4.z == 0.f) & (q4.w == 0.f) &
               (s0 == s1) & (s0 == s2c) & (s0 == sg0);
    }
    const int iso = __syncthreads_and(pred);

    if (!iso) {
        generic_path(mu_x, mu_y, mu_z, sigmas, rq, weight,
                     sbuf, m, t, x, y, z, out, n, N);
        return;
    }

    // iso coefficient build (tiny)
    if (t < GDIM) {
        const float kk = -0.72134752044448169f;  // -0.5 * log2(e)
        const float a = kk / (s0 * s0);
        const float b0 = -2.f * (a * m0);
        const float b1 = -2.f * (a * m1);
        const float b2 = -2.f * (a * m2);
        const float c = a * (m0 * m0 + m1 * m1 + m2 * m2);
        sbuf[t] = make_float4(b0, b1, b2, w * fast_exp2(c));
        if (t == 0) s_a = a;
    }
    __syncthreads();

    const float s2 = fmaf(z, z, fmaf(y, y, x * x));
    const float E = fast_exp2(s_a * s2);

    float acc0 = 0.f, acc1 = 0.f, acc2 = 0.f, acc3 = 0.f;
    #pragma unroll
    for (int g = 0; g < GDIM; g += 4) {
        const float4 B0 = sbuf[g + 0];
        const float4 B1 = sbuf[g + 1];
        const float4 B2 = sbuf[g + 2];
        const float4 B3 = sbuf[g + 3];
        const float q0 = fmaf(B0.x, x, fmaf(B0.y, y, B0.z * z));
        const float q1 = fmaf(B1.x, x, fmaf(B1.y, y, B1.z * z));
        const float q2 = fmaf(B2.x, x, fmaf(B2.y, y, B2.z * z));
        const float q3 = fmaf(B3.x, x, fmaf(B3.y, y, B3.z * z));
        acc0 = fmaf(B0.w, fast_exp2(q0), acc0);
        acc1 = fmaf(B1.w, fast_exp2(q1), acc1);
        acc2 = fmaf(B2.w, fast_exp2(q2), acc2);
        acc3 = fmaf(B3.w, fast_exp2(q3), acc3);
    }
    const float result = E * ((acc0 + acc1) + (acc2 + acc3));

    if (n < N) out[n * MDIM + m] = result;
}

extern "C" void kernel_launch(void* const* d_in, const int* in_sizes, int n_in,
                              void* d_out, int out_size) {
    const float* x      = (const float*)d_in[0];
    const float* y      = (const float*)d_in[1];
    const float* z      = (const float*)d_in[2];
    const float* mu_x   = (const float*)d_in[3];
    const float* mu_y   = (const float*)d_in[4];
    const float* mu_z   = (const float*)d_in[5];
    const float* sigmas = (const float*)d_in[6];
    const float* r      = (const float*)d_in[7];
    const float* weight = (const float*)d_in[8];
    float* out = (float*)d_out;

    const int N = in_sizes[0];

    dim3 grid((N + 255) / 256, MDIM);
    gauss_fused_kernel<<<grid, 256>>>(x, y, z, mu_x, mu_y, mu_z,
                                      sigmas, r, weight, out, N);
}

// round 7
// speedup vs baseline: 1.0335x; 1.0335x over previous
#include <cuda_runtime.h>
#include <cuda_bf16.h>

// M=64, G=48, N=4096, GRID_RANGE=2.0
// Inputs: 0:x(N) 1:y(N) 2:z(N) 3:mu_x(M*G) 4:mu_y(M*G) 5:mu_z(M*G)
//         6:sigmas(M*G*3) 7:r(M*G*4) 8:weight(M*G)
// Output: float (N, M) row-major.

#define MDIM 64
#define GDIM 48

__device__ __forceinline__ float fast_exp2(float q) {
    float p; asm("ex2.approx.ftz.f32 %0, %1;" : "=f"(p) : "f"(q)); return p;
}

// One m per block (blockIdx.y); 512 points per block, 2 per thread; grid.x = 8.
// Iso fast path (A = a*I, a common to all g):
//   out = exp2(a*|p|^2) * sum_g (w_g*exp2(c_g)) * exp2(b_g.p)
// Hot loop per (g, point): 0.5 LDS.128 {b0,b1,b2,w'}, 3 FMA, 1 MUFU, 1 acc FMA.
__global__ __launch_bounds__(256) void gauss_fused_kernel(
    const float* __restrict__ xs, const float* __restrict__ ys,
    const float* __restrict__ zs,
    const float* __restrict__ mu_x, const float* __restrict__ mu_y,
    const float* __restrict__ mu_z, const float* __restrict__ sigmas,
    const float* __restrict__ rq, const float* __restrict__ weight,
    float* __restrict__ out, int N) {
    __shared__ __align__(16) float4 sbuf[GDIM * 3];  // iso uses first 48
    __shared__ float s_a;

    const int m = blockIdx.y;
    const int t = threadIdx.x;
    const int n0 = blockIdx.x * 512 + t;
    const int n1 = n0 + 256;

    // ---- early point loads (independent of coefficient pipeline) ----
    float x0 = 0.f, y0 = 0.f, z0 = 0.f;
    float x1 = 0.f, y1 = 0.f, z1 = 0.f;
    if (n0 < N) { x0 = xs[n0]; y0 = ys[n0] + 1.f; z0 = zs[n0] + 1.f; }
    if (n1 < N) { x1 = xs[n1]; y1 = ys[n1] + 1.f; z1 = zs[n1] + 1.f; }

    // ---- iso detection from raw inputs ----
    int pred = 1;
    float s0 = 0.f, s1 = 0.f, s2c = 0.f;
    float m0 = 0.f, m1 = 0.f, m2 = 0.f, w = 0.f;
    float4 q4 = make_float4(1.f, 0.f, 0.f, 0.f);
    if (t < GDIM) {
        const int idx = m * GDIM + t;
        q4 = reinterpret_cast<const float4*>(rq)[idx];  // w,x,y,z
        s0  = sigmas[idx * 3 + 0];
        s1  = sigmas[idx * 3 + 1];
        s2c = sigmas[idx * 3 + 2];
        const float sg0 = sigmas[(m * GDIM) * 3];
        m0 = mu_x[idx]; m1 = mu_y[idx]; m2 = mu_z[idx];
        w = weight[idx];
        pred = (q4.y == 0.f) & (q4.z == 0.f) & (q4.w == 0.f) &
               (s0 == s1) & (s0 == s2c) & (s0 == sg0);
    }
    const int iso = __syncthreads_and(pred);

    float r0, r1;

    if (iso) {
        // ---- tiny iso coefficient build ----
        if (t < GDIM) {
            const float kk = -0.72134752044448169f;  // -0.5 * log2(e)
            const float a = kk / (s0 * s0);
            const float b0 = -2.f * (a * m0);
            const float b1 = -2.f * (a * m1);
            const float b2 = -2.f * (a * m2);
            const float c = a * (m0 * m0 + m1 * m1 + m2 * m2);
            sbuf[t] = make_float4(b0, b1, b2, w * fast_exp2(c));
            if (t == 0) s_a = a;
        }
        __syncthreads();

        const float s20 = fmaf(z0, z0, fmaf(y0, y0, x0 * x0));
        const float s21 = fmaf(z1, z1, fmaf(y1, y1, x1 * x1));
        const float a = s_a;
        const float E0 = fast_exp2(a * s20);
        const float E1 = fast_exp2(a * s21);

        float acc00 = 0.f, acc01 = 0.f, acc10 = 0.f, acc11 = 0.f;
        const float4* __restrict__ p = sbuf;
        #pragma unroll
        for (int g = 0; g < GDIM; g += 2, p += 2) {
            const float4 B0 = p[0];
            const float4 B1 = p[1];
            const float qa0 = fmaf(B0.x, x0, fmaf(B0.y, y0, B0.z * z0));
            const float qb0 = fmaf(B1.x, x0, fmaf(B1.y, y0, B1.z * z0));
            const float qa1 = fmaf(B0.x, x1, fmaf(B0.y, y1, B0.z * z1));
            const float qb1 = fmaf(B1.x, x1, fmaf(B1.y, y1, B1.z * z1));
            acc00 = fmaf(B0.w, fast_exp2(qa0), acc00);
            acc01 = fmaf(B1.w, fast_exp2(qb0), acc01);
            acc10 = fmaf(B0.w, fast_exp2(qa1), acc10);
            acc11 = fmaf(B1.w, fast_exp2(qb1), acc11);
        }
        r0 = E0 * (acc00 + acc01);
        r1 = E1 * (acc10 + acc11);
    } else {
        // ---- generic coefficient build ----
        if (t < GDIM) {
            const float inv = rsqrtf(q4.x * q4.x + q4.y * q4.y + q4.z * q4.z + q4.w * q4.w);
            const float nw = q4.x * inv, nx = q4.y * inv, ny = q4.z * inv, nz = q4.w * inv;
            float R[3][3];
            R[0][0] = 1.f - 2.f * (ny * ny + nz * nz);
            R[0][1] = 2.f * (nx * ny - nw * nz);
            R[0][2] = 2.f * (nx * nz + nw * ny);
            R[1][0] = 2.f * (nx * ny + nw * nz);
            R[1][1] = 1.f - 2.f * (nx * nx + nz * nz);
            R[1][2] = 2.f * (ny * nz - nw * nx);
            R[2][0] = 2.f * (nx * nz - nw * ny);
            R[2][1] = 2.f * (ny * nz + nw * nx);
            R[2][2] = 1.f - 2.f * (nx * nx + ny * ny);
            const float is0 = 1.f / (s0 * s0);
            const float is1 = 1.f / (s1 * s1);
            const float is2 = 1.f / (s2c * s2c);
            const float kk = -0.72134752044448169f;
            float A[3][3];
            #pragma unroll
            for (int i = 0; i < 3; ++i)
                #pragma unroll
                for (int j = 0; j < 3; ++j)
                    A[i][j] = kk * (R[i][0] * R[j][0] * is0 +
                                    R[i][1] * R[j][1] * is1 +
                                    R[i][2] * R[j][2] * is2);
            const float b0 = -2.f * (A[0][0] * m0 + A[0][1] * m1 + A[0][2] * m2);
            const float b1 = -2.f * (A[1][0] * m0 + A[1][1] * m1 + A[1][2] * m2);
            const float b2 = -2.f * (A[2][0] * m0 + A[2][1] * m1 + A[2][2] * m2);
            const float c  = A[0][0] * m0 * m0 + A[1][1] * m1 * m1 + A[2][2] * m2 * m2
                     + 2.f * (A[0][1] * m0 * m1 + A[0][2] * m0 * m2 + A[1][2] * m1 * m2);
            sbuf[t * 3 + 0] = make_float4(A[0][0], A[1][1], A[2][2], 2.f * A[0][1]);
            sbuf[t * 3 + 1] = make_float4(2.f * A[0][2], 2.f * A[1][2], b0, b1);
            sbuf[t * 3 + 2] = make_float4(b2, c, w, 0.f);
        }
        __syncthreads();

        const float xx0 = x0 * x0, yy0 = y0 * y0, zz0 = z0 * z0;
        const float xy0 = x0 * y0, xz0 = x0 * z0, yz0 = y0 * z0;
        const float xx1 = x1 * x1, yy1 = y1 * y1, zz1 = z1 * z1;
        const float xy1 = x1 * y1, xz1 = x1 * z1, yz1 = y1 * z1;
        float acc0 = 0.f, acc1 = 0.f;
        #pragma unroll 4
        for (int g = 0; g < GDIM; ++g) {
            const float4 cA = sbuf[g * 3 + 0];
            const float4 cB = sbuf[g * 3 + 1];
            const float4 cC = sbuf[g * 3 + 2];
            float qq0 = cC.y;
            qq0 = fmaf(cA.x, xx0, qq0);
            qq0 = fmaf(cA.y, yy0, qq0);
            qq0 = fmaf(cA.z, zz0, qq0);
            qq0 = fmaf(cA.w, xy0, qq0);
            qq0 = fmaf(cB.x, xz0, qq0);
            qq0 = fmaf(cB.y, yz0, qq0);
            qq0 = fmaf(cB.z, x0, qq0);
            qq0 = fmaf(cB.w, y0, qq0);
            qq0 = fmaf(cC.x, z0, qq0);
            float qq1 = cC.y;
            qq1 = fmaf(cA.x, xx1, qq1);
            qq1 = fmaf(cA.y, yy1, qq1);
            qq1 = fmaf(cA.z, zz1, qq1);
            qq1 = fmaf(cA.w, xy1, qq1);
            qq1 = fmaf(cB.x, xz1, qq1);
            qq1 = fmaf(cB.y, yz1, qq1);
            qq1 = fmaf(cB.z, x1, qq1);
            qq1 = fmaf(cB.w, y1, qq1);
            qq1 = fmaf(cC.x, z1, qq1);
            acc0 = fmaf(cC.z, fast_exp2(qq0), acc0);
            acc1 = fmaf(cC.z, fast_exp2(qq1), acc1);
        }
        r0 = acc0;
        r1 = acc1;
    }

    if (n0 < N) out[n0 * MDIM + m] = r0;
    if (n1 < N) out[n1 * MDIM + m] = r1;
}

extern "C" void kernel_launch(void* const* d_in, const int* in_sizes, int n_in,
                              void* d_out, int out_size) {
    const float* x      = (const float*)d_in[0];
    const float* y      = (const float*)d_in[1];
    const float* z      = (const float*)d_in[2];
    const float* mu_x   = (const float*)d_in[3];
    const float* mu_y   = (const float*)d_in[4];
    const float* mu_z   = (const float*)d_in[5];
    const float* sigmas = (const float*)d_in[6];
    const float* r      = (const float*)d_in[7];
    const float* weight = (const float*)d_in[8];
    float* out = (float*)d_out;

    const int N = in_sizes[0];

    dim3 grid((N + 511) / 512, MDIM);
    gauss_fused_kernel<<<grid, 256>>>(x, y, z, mu_x, mu_y, mu_z,
                                      sigmas, r, weight, out, N);
}